// round 9
// baseline (speedup 1.0000x reference)
#include <cuda_runtime.h>
#include <cstddef>

// B=4096, T=256, I=6, H=64, gates=3H=192, 2 GRU layers + FC(H->1)
#define T_STEPS 256
#define I_DIM   6
#define HDIM    64
#define G3      192
#define BB      32      // batches per CTA
#define NT      256     // 64 units x 4 batch-groups
#define NBPT    8       // batches per thread
#define PW      68      // weight row pitch (floats): conflict-free LDS.128
#define NCTA    128     // 4096 / 32

typedef unsigned long long u64;

// Packed fp32x2 ops (SASS FFMA2 / packed-add, PTX-only)
#define FFMA2(acc, a, b) \
    asm("fma.rn.f32x2 %0, %1, %2, %0;" : "+l"(acc) : "l"(a), "l"(b))
#define ADDX2(d, a, b) \
    asm("add.rn.f32x2 %0, %1, %2;" : "=l"(d) : "l"(a), "l"(b))

union F4U { float4 f; u64 u[2]; };
union F2U { float2 f; u64 u; };

struct SmemLayout {
    float Whh0[G3 * PW];
    float Wih1[G3 * PW];
    float Whh1[G3 * PW];
    float Wih0[G3 * 8];     // pitch 8 (I=6 used) -> float2-aligned pairs
    float bih0[G3];
    float bhh0[G3];
    float bih1[G3];
    float bhh1[G3];
    float h1[2][BB][HDIM];  // ping-pong hidden state, layer 0
    float h2[2][BB][HDIM];  // ping-pong hidden state, layer 1
    float xs[2][BB][8];     // pitch 8 for float2 pairing
    float wfc[HDIM];
    float bfc;
};

__device__ __forceinline__ float sigf(float v) {
    return __fdividef(1.0f, 1.0f + __expf(-v));
}
// tanh via MUFU exp: short dependency chain.
__device__ __forceinline__ float tanhfast(float v) {
    float c = fminf(fmaxf(v, -15.0f), 15.0f);
    float e = __expf(2.0f * c);
    return __fdividef(e - 1.0f, e + 1.0f);
}
__device__ __forceinline__ float hsum(u64 p) {
    F2U t; t.u = p;
    return t.f.x + t.f.y;
}
__device__ __forceinline__ u64 packbias(float b) {
    F2U t; t.f = make_float2(b, 0.0f);
    return t.u;
}

__global__ __launch_bounds__(NT) void gru_fused_kernel(
    const float* __restrict__ x,
    const float* __restrict__ W_ih0, const float* __restrict__ W_hh0,
    const float* __restrict__ b_ih0, const float* __restrict__ b_hh0,
    const float* __restrict__ W_ih1, const float* __restrict__ W_hh1,
    const float* __restrict__ b_ih1, const float* __restrict__ b_hh1,
    const float* __restrict__ W_fc,  const float* __restrict__ b_fc,
    float* __restrict__ out)
{
    extern __shared__ float smem_raw[];
    SmemLayout& s = *reinterpret_cast<SmemLayout*>(smem_raw);

    const int tid = threadIdx.x;
    const int b0  = blockIdx.x * BB;

    // ---- Stage weights into SMEM ----
    for (int i = tid; i < G3 * HDIM; i += NT) {
        int r = i >> 6, c = i & 63;
        s.Whh0[r * PW + c] = W_hh0[i];
        s.Wih1[r * PW + c] = W_ih1[i];
        s.Whh1[r * PW + c] = W_hh1[i];
    }
    for (int i = tid; i < G3 * 8; i += NT) s.Wih0[i] = 0.0f;   // pad
    for (int i = tid; i < BB * 8 * 2; i += NT) ((float*)s.xs)[i] = 0.0f;
    __syncthreads();
    for (int i = tid; i < G3 * I_DIM; i += NT)
        s.Wih0[(i / I_DIM) * 8 + (i % I_DIM)] = W_ih0[i];
    for (int i = tid; i < G3; i += NT) {
        s.bih0[i] = b_ih0[i];
        s.bhh0[i] = b_hh0[i];
        s.bih1[i] = b_ih1[i];
        s.bhh1[i] = b_hh1[i];
    }
    for (int i = tid; i < BB * HDIM; i += NT) {
        int b = i >> 6, c = i & 63;
        s.h1[0][b][c] = 0.0f;
        s.h2[0][b][c] = 0.0f;
    }
    if (tid < HDIM) s.wfc[tid] = W_fc[tid];
    if (tid == 0)   s.bfc = b_fc[0];

    // x prefetch lanes
    const bool is_pref_lane = (tid < BB * I_DIM);
    const int  lb = is_pref_lane ? (tid / I_DIM) : 0;
    const int  li = is_pref_lane ? (tid % I_DIM) : 0;
    const float* xlane = x + (size_t)(b0 + lb) * T_STEPS * I_DIM + li;
    if (is_pref_lane) s.xs[0][lb][li] = xlane[0];
    __syncthreads();

    // Mapping: gg = hidden unit (0..63); bg = tid>>6 (0..3) -> 8 batches each.
    const int gg  = tid & 63;
    const int bg  = tid >> 6;
    const int bb0 = bg * NBPT;
    const int gr = gg, gz = gg + 64, gn = gg + 128;

    const float* Whh0r = &s.Whh0[gr * PW];
    const float* Whh0z = &s.Whh0[gz * PW];
    const float* Whh0n = &s.Whh0[gn * PW];
    const float* Wih1r = &s.Wih1[gr * PW];
    const float* Wih1z = &s.Wih1[gz * PW];
    const float* Wih1n = &s.Wih1[gn * PW];
    const float* Whh1r = &s.Whh1[gr * PW];
    const float* Whh1z = &s.Whh1[gz * PW];
    const float* Whh1n = &s.Whh1[gn * PW];

    const u64 iR0 = packbias(s.bih0[gr] + s.bhh0[gr]);
    const u64 iZ0 = packbias(s.bih0[gz] + s.bhh0[gz]);
    const u64 iXN0 = packbias(s.bih0[gn]);
    const u64 iHN0 = packbias(s.bhh0[gn]);
    const u64 iR1 = packbias(s.bih1[gr] + s.bhh1[gr]);
    const u64 iZ1 = packbias(s.bih1[gz] + s.bhh1[gz]);
    const u64 iXN1 = packbias(s.bih1[gn]);
    const u64 iHN1 = packbias(s.bhh1[gn]);

    // ---- Layer bodies ----
    // L0(t): reads h1[cur], xs[cur]; writes h1[nxt].
    auto layer0 = [&](int cur, int nxt) {
        u64 accX[NBPT][3], accH[NBPT][3];
        #pragma unroll
        for (int b = 0; b < NBPT; ++b) {
            accX[b][0] = iR0;  accX[b][1] = iZ0;  accX[b][2] = iXN0;
            accH[b][0] = 0ull; accH[b][1] = 0ull; accH[b][2] = iHN0;
        }
        #pragma unroll
        for (int kp = 0; kp < 3; ++kp) {
            F2U w0; w0.f = *(const float2*)&s.Wih0[gr * 8 + 2 * kp];
            F2U w1; w1.f = *(const float2*)&s.Wih0[gz * 8 + 2 * kp];
            F2U w2; w2.f = *(const float2*)&s.Wih0[gn * 8 + 2 * kp];
            #pragma unroll
            for (int b = 0; b < NBPT; ++b) {
                F2U xv; xv.f = *(const float2*)&s.xs[cur][bb0 + b][2 * kp];
                FFMA2(accX[b][0], xv.u, w0.u);
                FFMA2(accX[b][1], xv.u, w1.u);
                FFMA2(accX[b][2], xv.u, w2.u);
            }
        }
        {   // recurrent GEMV, weights pipelined one chunk ahead
            F4U w0n, w1n, w2n;
            w0n.f = *(const float4*)&Whh0r[0];
            w1n.f = *(const float4*)&Whh0z[0];
            w2n.f = *(const float4*)&Whh0n[0];
            #pragma unroll
            for (int kc = 0; kc < 16; ++kc) {
                const int k = kc * 4;
                F4U w0 = w0n, w1 = w1n, w2 = w2n;
                if (kc < 15) {
                    w0n.f = *(const float4*)&Whh0r[k + 4];
                    w1n.f = *(const float4*)&Whh0z[k + 4];
                    w2n.f = *(const float4*)&Whh0n[k + 4];
                }
                #pragma unroll
                for (int b = 0; b < NBPT; ++b) {
                    F4U h; h.f = *(const float4*)&s.h1[cur][bb0 + b][k];
                    FFMA2(accH[b][0], h.u[0], w0.u[0]);
                    FFMA2(accH[b][0], h.u[1], w0.u[1]);
                    FFMA2(accH[b][1], h.u[0], w1.u[0]);
                    FFMA2(accH[b][1], h.u[1], w1.u[1]);
                    FFMA2(accH[b][2], h.u[0], w2.u[0]);
                    FFMA2(accH[b][2], h.u[1], w2.u[1]);
                }
            }
        }
        #pragma unroll
        for (int b = 0; b < NBPT; ++b) {
            u64 s0, s1;
            ADDX2(s0, accX[b][0], accH[b][0]);
            ADDX2(s1, accX[b][1], accH[b][1]);
            float r = sigf(hsum(s0));
            float z = sigf(hsum(s1));
            float n = tanhfast(fmaf(r, hsum(accH[b][2]), hsum(accX[b][2])));
            float hp = s.h1[cur][bb0 + b][gg];
            s.h1[nxt][bb0 + b][gg] = fmaf(z, hp - n, n);
        }
    };

    // L1(s) at iter t=s+1: reads h1[cur] (= h1_s), h2[nxt] (= h2_{s-1});
    // writes h2[cur] (= h2_s).
    auto layer1 = [&](int cur, int nxt) {
        u64 accX[NBPT][3], accH[NBPT][3];
        #pragma unroll
        for (int b = 0; b < NBPT; ++b) {
            accX[b][0] = iR1;  accX[b][1] = iZ1;  accX[b][2] = iXN1;
            accH[b][0] = 0ull; accH[b][1] = 0ull; accH[b][2] = iHN1;
        }
        {
            F4U u0n, u1n, u2n, v0n, v1n, v2n;
            u0n.f = *(const float4*)&Wih1r[0];
            u1n.f = *(const float4*)&Wih1z[0];
            u2n.f = *(const float4*)&Wih1n[0];
            v0n.f = *(const float4*)&Whh1r[0];
            v1n.f = *(const float4*)&Whh1z[0];
            v2n.f = *(const float4*)&Whh1n[0];
            #pragma unroll 4
            for (int kc = 0; kc < 16; ++kc) {
                const int k = kc * 4;
                F4U u0 = u0n, u1 = u1n, u2 = u2n;
                F4U v0 = v0n, v1 = v1n, v2 = v2n;
                if (kc < 15) {
                    u0n.f = *(const float4*)&Wih1r[k + 4];
                    u1n.f = *(const float4*)&Wih1z[k + 4];
                    u2n.f = *(const float4*)&Wih1n[k + 4];
                    v0n.f = *(const float4*)&Whh1r[k + 4];
                    v1n.f = *(const float4*)&Whh1z[k + 4];
                    v2n.f = *(const float4*)&Whh1n[k + 4];
                }
                #pragma unroll
                for (int b = 0; b < NBPT; ++b) {
                    F4U p; p.f = *(const float4*)&s.h1[cur][bb0 + b][k];
                    F4U q; q.f = *(const float4*)&s.h2[nxt][bb0 + b][k];
                    FFMA2(accX[b][0], p.u[0], u0.u[0]);
                    FFMA2(accX[b][0], p.u[1], u0.u[1]);
                    FFMA2(accX[b][1], p.u[0], u1.u[0]);
                    FFMA2(accX[b][1], p.u[1], u1.u[1]);
                    FFMA2(accX[b][2], p.u[0], u2.u[0]);
                    FFMA2(accX[b][2], p.u[1], u2.u[1]);
                    FFMA2(accH[b][0], q.u[0], v0.u[0]);
                    FFMA2(accH[b][0], q.u[1], v0.u[1]);
                    FFMA2(accH[b][1], q.u[0], v1.u[0]);
                    FFMA2(accH[b][1], q.u[1], v1.u[1]);
                    FFMA2(accH[b][2], q.u[0], v2.u[0]);
                    FFMA2(accH[b][2], q.u[1], v2.u[1]);
                }
            }
        }
        #pragma unroll
        for (int b = 0; b < NBPT; ++b) {
            u64 s0, s1;
            ADDX2(s0, accX[b][0], accH[b][0]);
            ADDX2(s1, accX[b][1], accH[b][1]);
            float r = sigf(hsum(s0));
            float z = sigf(hsum(s1));
            float n = tanhfast(fmaf(r, hsum(accH[b][2]), hsum(accX[b][2])));
            float hp = s.h2[nxt][bb0 + b][gg];
            s.h2[cur][bb0 + b][gg] = fmaf(z, hp - n, n);
        }
    };

    // ---- Pipelined time loop: one barrier per step ----
    // Peel: L0(0)
    {
        if (is_pref_lane) s.xs[1][lb][li] = xlane[I_DIM];   // x for t=1
        layer0(0, 1);
        __syncthreads();
    }
    for (int t = 1; t < T_STEPS; ++t) {
        const int cur = t & 1, nxt = cur ^ 1;

        float xpref = 0.0f;
        const bool do_pref = is_pref_lane && (t + 1 < T_STEPS);
        if (do_pref) xpref = xlane[(size_t)(t + 1) * I_DIM];

        layer0(cur, nxt);   // L0(t):   h1_{t-1} -> h1_t
        layer1(cur, nxt);   // L1(t-1): h1_{t-1}, h2_{t-2} -> h2_{t-1}

        if (do_pref) s.xs[nxt][lb][li] = xpref;
        __syncthreads();
    }
    // Peel: L1(255). t would be 256: cur=0, nxt=1.
    layer1(0, 1);
    __syncthreads();

    // ---- Final FC: h2_255 is in buffer 0 ----
    if (tid < BB) {
        float acc = s.bfc;
        #pragma unroll 8
        for (int k = 0; k < HDIM; ++k)
            acc = fmaf(s.h2[0][tid][k], s.wfc[k], acc);
        out[b0 + tid] = acc;
    }
}

extern "C" void kernel_launch(void* const* d_in, const int* in_sizes, int n_in,
                              void* d_out, int out_size)
{
    const float* x     = (const float*)d_in[0];
    const float* W_ih0 = (const float*)d_in[1];
    const float* W_hh0 = (const float*)d_in[2];
    const float* b_ih0 = (const float*)d_in[3];
    const float* b_hh0 = (const float*)d_in[4];
    const float* W_ih1 = (const float*)d_in[5];
    const float* W_hh1 = (const float*)d_in[6];
    const float* b_ih1 = (const float*)d_in[7];
    const float* b_hh1 = (const float*)d_in[8];
    const float* W_fc  = (const float*)d_in[9];
    const float* b_fc  = (const float*)d_in[10];
    float* out = (float*)d_out;

    (void)in_sizes; (void)n_in; (void)out_size;

    static_assert(sizeof(SmemLayout) < 227 * 1024, "smem over budget");
    cudaFuncSetAttribute(gru_fused_kernel,
                         cudaFuncAttributeMaxDynamicSharedMemorySize,
                         (int)sizeof(SmemLayout));

    gru_fused_kernel<<<NCTA, NT, sizeof(SmemLayout)>>>(
        x, W_ih0, W_hh0, b_ih0, b_hh0,
        W_ih1, W_hh1, b_ih1, b_hh1,
        W_fc, b_fc, out);
}

// round 10
// speedup vs baseline: 1.0680x; 1.0680x over previous
#include <cuda_runtime.h>
#include <cstddef>

// B=4096, T=256, I=6, H=64, gates=3H=192, 2 GRU layers + FC(H->1)
#define T_STEPS 256
#define I_DIM   6
#define HDIM    64
#define G3      192
#define BB      32      // batches per CTA
#define NT      256     // 64 units x 4 batch-groups
#define NBPT    8       // batches per thread
#define PW      68      // weight row pitch (floats): conflict-free LDS.128
#define NCTA    128     // 4096 / 32

typedef unsigned long long u64;

// Packed fp32x2 FMA (SASS FFMA2, PTX-only)
#define FFMA2(acc, a, b) \
    asm("fma.rn.f32x2 %0, %1, %2, %0;" : "+l"(acc) : "l"(a), "l"(b))

union F4U { float4 f; u64 u[2]; };
union F2U { float2 f; u64 u; };

struct SmemLayout {
    float Whh0[G3 * PW];
    float Wih1[G3 * PW];
    float Whh1[G3 * PW];
    float Wih0[G3 * 8];     // pitch 8 (I=6 used) -> float2-aligned pairs
    float bih0[G3];
    float bhh0[G3];
    float bih1[G3];
    float bhh1[G3];
    float h1[2][BB][HDIM];  // ping-pong hidden state, layer 0
    float h2[2][BB][HDIM];  // ping-pong hidden state, layer 1
    float xs[2][BB][8];     // pitch 8 for float2 pairing
    float wfc[HDIM];
    float bfc;
};

__device__ __forceinline__ float sigf(float v) {
    return __fdividef(1.0f, 1.0f + __expf(-v));
}
__device__ __forceinline__ float tanhfast(float v) {
    float c = fminf(fmaxf(v, -15.0f), 15.0f);
    float e = __expf(2.0f * c);
    return __fdividef(e - 1.0f, e + 1.0f);
}
__device__ __forceinline__ float hsum(u64 p) {
    F2U t; t.u = p;
    return t.f.x + t.f.y;
}
__device__ __forceinline__ u64 packbias(float b) {
    F2U t; t.f = make_float2(b, 0.0f);
    return t.u;
}

__global__ __launch_bounds__(NT) void gru_fused_kernel(
    const float* __restrict__ x,
    const float* __restrict__ W_ih0, const float* __restrict__ W_hh0,
    const float* __restrict__ b_ih0, const float* __restrict__ b_hh0,
    const float* __restrict__ W_ih1, const float* __restrict__ W_hh1,
    const float* __restrict__ b_ih1, const float* __restrict__ b_hh1,
    const float* __restrict__ W_fc,  const float* __restrict__ b_fc,
    float* __restrict__ out)
{
    extern __shared__ float smem_raw[];
    SmemLayout& s = *reinterpret_cast<SmemLayout*>(smem_raw);

    const int tid = threadIdx.x;
    const int b0  = blockIdx.x * BB;

    // ---- Stage weights into SMEM ----
    for (int i = tid; i < G3 * HDIM; i += NT) {
        int r = i >> 6, c = i & 63;
        s.Whh0[r * PW + c] = W_hh0[i];
        s.Wih1[r * PW + c] = W_ih1[i];
        s.Whh1[r * PW + c] = W_hh1[i];
    }
    for (int i = tid; i < G3 * 8; i += NT) s.Wih0[i] = 0.0f;   // pad
    for (int i = tid; i < BB * 8 * 2; i += NT) ((float*)s.xs)[i] = 0.0f;
    __syncthreads();
    for (int i = tid; i < G3 * I_DIM; i += NT)
        s.Wih0[(i / I_DIM) * 8 + (i % I_DIM)] = W_ih0[i];
    for (int i = tid; i < G3; i += NT) {
        s.bih0[i] = b_ih0[i];
        s.bhh0[i] = b_hh0[i];
        s.bih1[i] = b_ih1[i];
        s.bhh1[i] = b_hh1[i];
    }
    for (int i = tid; i < BB * HDIM; i += NT) {
        int b = i >> 6, c = i & 63;
        s.h1[0][b][c] = 0.0f;
        s.h2[0][b][c] = 0.0f;
    }
    if (tid < HDIM) s.wfc[tid] = W_fc[tid];
    if (tid == 0)   s.bfc = b_fc[0];

    // x prefetch lanes
    const bool is_pref_lane = (tid < BB * I_DIM);
    const int  lb = is_pref_lane ? (tid / I_DIM) : 0;
    const int  li = is_pref_lane ? (tid % I_DIM) : 0;
    const float* xlane = x + (size_t)(b0 + lb) * T_STEPS * I_DIM + li;
    if (is_pref_lane) s.xs[0][lb][li] = xlane[0];
    __syncthreads();

    // Mapping: gg = hidden unit (0..63); bg = tid>>6 (0..3) -> 8 batches each.
    const int gg  = tid & 63;
    const int bg  = tid >> 6;
    const int bb0 = bg * NBPT;
    const int gr = gg, gz = gg + 64, gn = gg + 128;

    const float* Whh0r = &s.Whh0[gr * PW];
    const float* Whh0z = &s.Whh0[gz * PW];
    const float* Whh0n = &s.Whh0[gn * PW];
    const float* Wih1r = &s.Wih1[gr * PW];
    const float* Wih1z = &s.Wih1[gz * PW];
    const float* Wih1n = &s.Wih1[gn * PW];
    const float* Whh1r = &s.Whh1[gr * PW];
    const float* Whh1z = &s.Whh1[gz * PW];
    const float* Whh1n = &s.Whh1[gn * PW];

    const u64 iR0 = packbias(s.bih0[gr] + s.bhh0[gr]);
    const u64 iZ0 = packbias(s.bih0[gz] + s.bhh0[gz]);
    const u64 iXN0 = packbias(s.bih0[gn]);
    const u64 iHN0 = packbias(s.bhh0[gn]);
    const u64 iR1 = packbias(s.bih1[gr] + s.bhh1[gr]);
    const u64 iZ1 = packbias(s.bih1[gz] + s.bhh1[gz]);
    const u64 iXN1 = packbias(s.bih1[gn]);
    const u64 iHN1 = packbias(s.bhh1[gn]);

    // ---- Solo layer bodies (pipeline peels only) ----
    auto layer0_solo = [&](int cur, int nxt) {
        u64 aR[NBPT], aZ[NBPT], aXN[NBPT], aHN[NBPT];
        #pragma unroll
        for (int b = 0; b < NBPT; ++b) {
            aR[b] = iR0; aZ[b] = iZ0; aXN[b] = iXN0; aHN[b] = iHN0;
        }
        #pragma unroll
        for (int kp = 0; kp < 3; ++kp) {
            F2U w0; w0.f = *(const float2*)&s.Wih0[gr * 8 + 2 * kp];
            F2U w1; w1.f = *(const float2*)&s.Wih0[gz * 8 + 2 * kp];
            F2U w2; w2.f = *(const float2*)&s.Wih0[gn * 8 + 2 * kp];
            #pragma unroll
            for (int b = 0; b < NBPT; ++b) {
                F2U xv; xv.f = *(const float2*)&s.xs[cur][bb0 + b][2 * kp];
                FFMA2(aR[b],  xv.u, w0.u);
                FFMA2(aZ[b],  xv.u, w1.u);
                FFMA2(aXN[b], xv.u, w2.u);
            }
        }
        #pragma unroll 4
        for (int kc = 0; kc < 16; ++kc) {
            const int k = kc * 4;
            F4U w0; w0.f = *(const float4*)&Whh0r[k];
            F4U w1; w1.f = *(const float4*)&Whh0z[k];
            F4U w2; w2.f = *(const float4*)&Whh0n[k];
            #pragma unroll
            for (int b = 0; b < NBPT; ++b) {
                F4U h; h.f = *(const float4*)&s.h1[cur][bb0 + b][k];
                FFMA2(aR[b],  h.u[0], w0.u[0]);
                FFMA2(aR[b],  h.u[1], w0.u[1]);
                FFMA2(aZ[b],  h.u[0], w1.u[0]);
                FFMA2(aZ[b],  h.u[1], w1.u[1]);
                FFMA2(aHN[b], h.u[0], w2.u[0]);
                FFMA2(aHN[b], h.u[1], w2.u[1]);
            }
        }
        #pragma unroll
        for (int b = 0; b < NBPT; ++b) {
            float r = sigf(hsum(aR[b]));
            float z = sigf(hsum(aZ[b]));
            float n = tanhfast(fmaf(r, hsum(aHN[b]), hsum(aXN[b])));
            float hp = s.h1[cur][bb0 + b][gg];
            s.h1[nxt][bb0 + b][gg] = fmaf(z, hp - n, n);
        }
    };

    auto layer1_solo = [&](int cur, int nxt) {
        u64 aR[NBPT], aZ[NBPT], aXN[NBPT], aHN[NBPT];
        #pragma unroll
        for (int b = 0; b < NBPT; ++b) {
            aR[b] = iR1; aZ[b] = iZ1; aXN[b] = iXN1; aHN[b] = iHN1;
        }
        #pragma unroll 4
        for (int kc = 0; kc < 16; ++kc) {
            const int k = kc * 4;
            F4U u0; u0.f = *(const float4*)&Wih1r[k];
            F4U u1; u1.f = *(const float4*)&Wih1z[k];
            F4U u2; u2.f = *(const float4*)&Wih1n[k];
            F4U v0; v0.f = *(const float4*)&Whh1r[k];
            F4U v1; v1.f = *(const float4*)&Whh1z[k];
            F4U v2; v2.f = *(const float4*)&Whh1n[k];
            #pragma unroll
            for (int b = 0; b < NBPT; ++b) {
                F4U p; p.f = *(const float4*)&s.h1[cur][bb0 + b][k];
                F4U q; q.f = *(const float4*)&s.h2[nxt][bb0 + b][k];
                FFMA2(aR[b],  p.u[0], u0.u[0]);
                FFMA2(aR[b],  p.u[1], u0.u[1]);
                FFMA2(aZ[b],  p.u[0], u1.u[0]);
                FFMA2(aZ[b],  p.u[1], u1.u[1]);
                FFMA2(aXN[b], p.u[0], u2.u[0]);
                FFMA2(aXN[b], p.u[1], u2.u[1]);
                FFMA2(aR[b],  q.u[0], v0.u[0]);
                FFMA2(aR[b],  q.u[1], v0.u[1]);
                FFMA2(aZ[b],  q.u[0], v1.u[0]);
                FFMA2(aZ[b],  q.u[1], v1.u[1]);
                FFMA2(aHN[b], q.u[0], v2.u[0]);
                FFMA2(aHN[b], q.u[1], v2.u[1]);
            }
        }
        #pragma unroll
        for (int b = 0; b < NBPT; ++b) {
            float r = sigf(hsum(aR[b]));
            float z = sigf(hsum(aZ[b]));
            float n = tanhfast(fmaf(r, hsum(aHN[b]), hsum(aXN[b])));
            float hp = s.h2[nxt][bb0 + b][gg];
            s.h2[cur][bb0 + b][gg] = fmaf(z, hp - n, n);
        }
    };

    // ---- Pipelined time loop, fused L0(t)+L1(t-1), one barrier/step ----
    {
        if (is_pref_lane) s.xs[1][lb][li] = xlane[I_DIM];   // x for t=1
        layer0_solo(0, 1);
        __syncthreads();
    }
    for (int t = 1; t < T_STEPS; ++t) {
        const int cur = t & 1, nxt = cur ^ 1;

        float xpref = 0.0f;
        const bool do_pref = is_pref_lane && (t + 1 < T_STEPS);
        if (do_pref) xpref = xlane[(size_t)(t + 1) * I_DIM];

        // Accumulators: 4 per batch per layer (r/z folded; n split for gating)
        u64 aR0[NBPT], aZ0[NBPT], aXN0[NBPT], aHN0[NBPT];
        u64 aR1[NBPT], aZ1[NBPT], aXN1[NBPT], aHN1[NBPT];
        #pragma unroll
        for (int b = 0; b < NBPT; ++b) {
            aR0[b] = iR0; aZ0[b] = iZ0; aXN0[b] = iXN0; aHN0[b] = iHN0;
            aR1[b] = iR1; aZ1[b] = iZ1; aXN1[b] = iXN1; aHN1[b] = iHN1;
        }
        // L0 input GEMV (I=6)
        #pragma unroll
        for (int kp = 0; kp < 3; ++kp) {
            F2U w0; w0.f = *(const float2*)&s.Wih0[gr * 8 + 2 * kp];
            F2U w1; w1.f = *(const float2*)&s.Wih0[gz * 8 + 2 * kp];
            F2U w2; w2.f = *(const float2*)&s.Wih0[gn * 8 + 2 * kp];
            #pragma unroll
            for (int b = 0; b < NBPT; ++b) {
                F2U xv; xv.f = *(const float2*)&s.xs[cur][bb0 + b][2 * kp];
                FFMA2(aR0[b],  xv.u, w0.u);
                FFMA2(aZ0[b],  xv.u, w1.u);
                FFMA2(aXN0[b], xv.u, w2.u);
            }
        }
        // Fused k-loop: h = h1[cur] feeds BOTH L0 recurrent (3 gates) and
        // L1 input (3 gates); q = h2[nxt] feeds L1 recurrent. Two fully
        // independent dependency streams -> latency of one hides the other.
        #pragma unroll 4
        for (int kc = 0; kc < 16; ++kc) {
            const int k = kc * 4;
            F4U w0; w0.f = *(const float4*)&Whh0r[k];
            F4U w1; w1.f = *(const float4*)&Whh0z[k];
            F4U w2; w2.f = *(const float4*)&Whh0n[k];
            F4U u0; u0.f = *(const float4*)&Wih1r[k];
            F4U u1; u1.f = *(const float4*)&Wih1z[k];
            F4U u2; u2.f = *(const float4*)&Wih1n[k];
            F4U v0; v0.f = *(const float4*)&Whh1r[k];
            F4U v1; v1.f = *(const float4*)&Whh1z[k];
            F4U v2; v2.f = *(const float4*)&Whh1n[k];
            #pragma unroll
            for (int b = 0; b < NBPT; ++b) {
                F4U h; h.f = *(const float4*)&s.h1[cur][bb0 + b][k];
                F4U q; q.f = *(const float4*)&s.h2[nxt][bb0 + b][k];
                FFMA2(aR0[b],  h.u[0], w0.u[0]);
                FFMA2(aR0[b],  h.u[1], w0.u[1]);
                FFMA2(aZ0[b],  h.u[0], w1.u[0]);
                FFMA2(aZ0[b],  h.u[1], w1.u[1]);
                FFMA2(aHN0[b], h.u[0], w2.u[0]);
                FFMA2(aHN0[b], h.u[1], w2.u[1]);
                FFMA2(aR1[b],  h.u[0], u0.u[0]);
                FFMA2(aR1[b],  h.u[1], u0.u[1]);
                FFMA2(aZ1[b],  h.u[0], u1.u[0]);
                FFMA2(aZ1[b],  h.u[1], u1.u[1]);
                FFMA2(aXN1[b], h.u[0], u2.u[0]);
                FFMA2(aXN1[b], h.u[1], u2.u[1]);
                FFMA2(aR1[b],  q.u[0], v0.u[0]);
                FFMA2(aR1[b],  q.u[1], v0.u[1]);
                FFMA2(aZ1[b],  q.u[0], v1.u[0]);
                FFMA2(aZ1[b],  q.u[1], v1.u[1]);
                FFMA2(aHN1[b], q.u[0], v2.u[0]);
                FFMA2(aHN1[b], q.u[1], v2.u[1]);
            }
        }
        // L0(t) tail -> h1[nxt]
        #pragma unroll
        for (int b = 0; b < NBPT; ++b) {
            float r = sigf(hsum(aR0[b]));
            float z = sigf(hsum(aZ0[b]));
            float n = tanhfast(fmaf(r, hsum(aHN0[b]), hsum(aXN0[b])));
            float hp = s.h1[cur][bb0 + b][gg];
            s.h1[nxt][bb0 + b][gg] = fmaf(z, hp - n, n);
        }
        // L1(t-1) tail -> h2[cur]
        #pragma unroll
        for (int b = 0; b < NBPT; ++b) {
            float r = sigf(hsum(aR1[b]));
            float z = sigf(hsum(aZ1[b]));
            float n = tanhfast(fmaf(r, hsum(aHN1[b]), hsum(aXN1[b])));
            float hp = s.h2[nxt][bb0 + b][gg];
            s.h2[cur][bb0 + b][gg] = fmaf(z, hp - n, n);
        }
        if (do_pref) s.xs[nxt][lb][li] = xpref;
        __syncthreads();
    }
    // Peel: L1(255). Virtual t=256: cur=0, nxt=1.
    layer1_solo(0, 1);
    __syncthreads();

    // ---- Final FC: h2_255 is in buffer 0 ----
    if (tid < BB) {
        float acc = s.bfc;
        #pragma unroll 8
        for (int k = 0; k < HDIM; ++k)
            acc = fmaf(s.h2[0][tid][k], s.wfc[k], acc);
        out[b0 + tid] = acc;
    }
}

extern "C" void kernel_launch(void* const* d_in, const int* in_sizes, int n_in,
                              void* d_out, int out_size)
{
    const float* x     = (const float*)d_in[0];
    const float* W_ih0 = (const float*)d_in[1];
    const float* W_hh0 = (const float*)d_in[2];
    const float* b_ih0 = (const float*)d_in[3];
    const float* b_hh0 = (const float*)d_in[4];
    const float* W_ih1 = (const float*)d_in[5];
    const float* W_hh1 = (const float*)d_in[6];
    const float* b_ih1 = (const float*)d_in[7];
    const float* b_hh1 = (const float*)d_in[8];
    const float* W_fc  = (const float*)d_in[9];
    const float* b_fc  = (const float*)d_in[10];
    float* out = (float*)d_out;

    (void)in_sizes; (void)n_in; (void)out_size;

    static_assert(sizeof(SmemLayout) < 227 * 1024, "smem over budget");
    cudaFuncSetAttribute(gru_fused_kernel,
                         cudaFuncAttributeMaxDynamicSharedMemorySize,
                         (int)sizeof(SmemLayout));

    gru_fused_kernel<<<NCTA, NT, sizeof(SmemLayout)>>>(
        x, W_ih0, W_hh0, b_ih0, b_hh0,
        W_ih1, W_hh1, b_ih1, b_hh1,
        W_fc, b_fc, out);
}